// round 13
// baseline (speedup 1.0000x reference)
#include <cuda_runtime.h>
#include <math.h>
#include <stdint.h>

// ---------------- problem constants ----------------
#define S_   8192
#define H_   16
#define D_   128
#define HD_  2048
#define C_   12
#define MP_  12
#define CTX_ 24
#define POS_ 13
#define NBLK_ 683          // ceil(8192/12)
#define KSPLIT_ 16

// scratch (device globals: allocation-free rule)
__device__ float g_q[(size_t)S_ * HD_];
__device__ float g_k[(size_t)S_ * HD_];
__device__ float g_v[(size_t)S_ * HD_];
__device__ float g_ctx[(size_t)S_ * HD_];
__device__ float g_xr[(size_t)S_ * HD_];
__device__ float g_wt0[(size_t)HD_ * HD_];
__device__ float g_wt1[(size_t)HD_ * HD_];
__device__ float g_wt2[(size_t)HD_ * HD_];
__device__ float g_wt3[(size_t)HD_ * HD_];
__device__ float g_relk[(size_t)POS_ * HD_];
__device__ float g_relpart[(size_t)KSPLIT_ * POS_ * HD_];

// ---------------- small PTX helpers ----------------
__device__ __forceinline__ uint32_t smem_u32(const void* p) {
    uint32_t a;
    asm("{ .reg .u64 t; cvta.to.shared.u64 t, %1; cvt.u32.u64 %0, t; }" : "=r"(a) : "l"(p));
    return a;
}
__device__ __forceinline__ float rtf32(float x) {
    uint32_t r;
    asm("cvt.rna.tf32.f32 %0, %1;" : "=r"(r) : "f"(x));
    return __uint_as_float(r);
}
__device__ __forceinline__ void cp_async16(uint32_t dst, const void* src) {
    asm volatile("cp.async.cg.shared.global [%0], [%1], 16;" :: "r"(dst), "l"(src) : "memory");
}
__device__ __forceinline__ void cp_commit() {
    asm volatile("cp.async.commit_group;" ::: "memory");
}
__device__ __forceinline__ void mma_tf32(float* d, const uint32_t* a, const uint32_t* b) {
    asm volatile("mma.sync.aligned.m16n8k8.row.col.f32.tf32.tf32.f32 "
                 "{%0,%1,%2,%3}, {%4,%5,%6,%7}, {%8,%9}, {%0,%1,%2,%3};"
                 : "+f"(d[0]), "+f"(d[1]), "+f"(d[2]), "+f"(d[3])
                 : "r"(a[0]), "r"(a[1]), "r"(a[2]), "r"(a[3]), "r"(b[0]), "r"(b[1]));
}

// ---------------- tf32 mma.sync GEMM ----------------
// C[M,2048] = A[M,2048] @ W[2048,2048]   (W row-major [K][N])
// CTA 128x128, BK=32, 3-stage cp.async, 8 warps (4 m x 2 n), warp tile 32x64.
// One __syncthreads per 32-K iter (half of R8); refill-first; 2 CTAs/SM.
#define BM_  128
#define BN_  128
#define BK_  32
#define NST_ 3
#define ASTR_ 36            // A smem row stride (floats): (4r+c) mod 32 distinct
#define BSTR_ 136           // B smem row stride (floats), conflict-free
#define A_SZ_ (BM_ * ASTR_)             // 4608 floats
#define B_SZ_ (BK_ * BSTR_)             // 4352 floats
#define STG_SZ_ (A_SZ_ + B_SZ_)         // 8960 floats
#define GSMEM_ (NST_ * STG_SZ_ * 4)     // 107520 bytes
#define NIT_  (HD_ / BK_)               // 64

struct GemmBody {
    const float* agp;   // A global base for this thread
    const float* wgp;   // W global base for this thread
    uint32_t sb;
    int arow0, acol0, brow0, bcol0;

    __device__ __forceinline__ void stage_load(int s, int k0) const {
        uint32_t as = sb + (uint32_t)(s * STG_SZ_) * 4;
        uint32_t bs = as + A_SZ_ * 4;
        // A: 128 rows x 32 floats = 1024 16B-chunks, 4 per thread
#pragma unroll
        for (int i = 0; i < 4; i++)
            cp_async16(as + (((arow0 + i * 32) * ASTR_ + acol0) * 4),
                       agp + (size_t)(i * 32) * HD_ + k0);
        // B: 32 rows x 128 floats = 1024 16B-chunks, 4 per thread
#pragma unroll
        for (int i = 0; i < 4; i++)
            cp_async16(bs + (((brow0 + i * 8) * BSTR_ + bcol0) * 4),
                       wgp + (size_t)(k0 + i * 8) * HD_);
    }
};

__global__ void __launch_bounds__(256, 2)
gemm_mma_qkv(const float* __restrict__ A,
             const float* __restrict__ W0, const float* __restrict__ W1,
             const float* __restrict__ W2,
             float* __restrict__ C0, float* __restrict__ C1, float* __restrict__ C2)
{
    extern __shared__ float smem[];
    const int tid  = threadIdx.x;
    const int warp = tid >> 5;
    const int lane = tid & 31;
    const int wm   = warp & 3;          // m offset wm*32
    const int wn   = warp >> 2;         // n offset wn*64
    const int brow = blockIdx.y * BM_;
    const int bcol = blockIdx.x * BN_;
    const int r    = lane >> 2;         // 0..7
    const int c    = lane & 3;          // 0..3

    const float* W = (blockIdx.z == 0) ? W0 : (blockIdx.z == 1) ? W1 : W2;
    float* Cc      = (blockIdx.z == 0) ? C0 : (blockIdx.z == 1) ? C1 : C2;

    GemmBody gb;
    // A chunks: ch = tid + i*256 -> arow = ch>>3 (0..127), acol = (ch&7)*4
    gb.arow0 = tid >> 3;                // 0..31
    gb.acol0 = (tid & 7) * 4;           // 0..28
    // B chunks: ch = tid + i*256 -> brow = ch>>5 (0..31), bcol = (ch&31)*4
    gb.brow0 = tid >> 5;                // 0..7
    gb.bcol0 = (tid & 31) * 4;          // 0..124
    gb.agp = A + (size_t)(brow + gb.arow0) * HD_ + gb.acol0;
    gb.wgp = W + (size_t)gb.brow0 * HD_ + bcol + gb.bcol0;
    gb.sb  = smem_u32(smem);

    float acc[2][8][4];
#pragma unroll
    for (int i = 0; i < 2; i++)
#pragma unroll
        for (int j = 0; j < 8; j++)
#pragma unroll
            for (int e = 0; e < 4; e++) acc[i][j][e] = 0.f;

    // prologue: stages 0..NST-2
#pragma unroll
    for (int s = 0; s < NST_ - 1; s++) {
        gb.stage_load(s, s * BK_);
        cp_commit();
    }

    int sc = 0;              // stage being computed
    int sl = NST_ - 1;       // stage being loaded
    for (int it = 0; it < NIT_; it++) {
        asm volatile("cp.async.wait_group %0;" :: "n"(NST_ - 2) : "memory");
        __syncthreads();
        // barrier proves: stage sc loaded; all warps finished reading stage sl
        if (it + NST_ - 1 < NIT_)
            gb.stage_load(sl, (it + NST_ - 1) * BK_);
        cp_commit();

        const float* As = smem + sc * STG_SZ_;
        const float* Bs = As + A_SZ_;

#pragma unroll
        for (int ks = 0; ks < 4; ks++) {
            const int kc = c + ks * 8;
            uint32_t af[2][4];
#pragma unroll
            for (int i = 0; i < 2; i++) {
                const int row = wm * 32 + i * 16 + r;
                af[i][0] = __float_as_uint(As[row * ASTR_ + kc]);
                af[i][1] = __float_as_uint(As[(row + 8) * ASTR_ + kc]);
                af[i][2] = __float_as_uint(As[row * ASTR_ + kc + 4]);
                af[i][3] = __float_as_uint(As[(row + 8) * ASTR_ + kc + 4]);
            }
            uint32_t bf[8][2];
#pragma unroll
            for (int j = 0; j < 8; j++) {
                const int n = wn * 64 + j * 8 + r;
                bf[j][0] = __float_as_uint(Bs[kc * BSTR_ + n]);
                bf[j][1] = __float_as_uint(Bs[(kc + 4) * BSTR_ + n]);
            }
#pragma unroll
            for (int i = 0; i < 2; i++)
#pragma unroll
                for (int j = 0; j < 8; j++)
                    mma_tf32(acc[i][j], af[i], bf[j]);
        }
        sc = (sc == NST_ - 1) ? 0 : sc + 1;
        sl = (sl == NST_ - 1) ? 0 : sl + 1;
    }

    // epilogue: direct global stores (float2, d-fragment layout)
#pragma unroll
    for (int i = 0; i < 2; i++) {
        const int row0 = brow + wm * 32 + i * 16 + r;
#pragma unroll
        for (int j = 0; j < 8; j++) {
            const int col = bcol + wn * 64 + j * 8 + c * 2;
            *(float2*)(Cc + (size_t)row0 * HD_ + col)       = make_float2(acc[i][j][0], acc[i][j][1]);
            *(float2*)(Cc + (size_t)(row0 + 8) * HD_ + col) = make_float2(acc[i][j][2], acc[i][j][3]);
        }
    }
}

// ---------------- fused tf32 rounding (X + 4 weights in one launch) ----------------
#define NX4_ (S_ * HD_ / 4)
#define NW4_ (HD_ * HD_ / 4)
__global__ void round_all(const float* __restrict__ x,
                          const float* __restrict__ wq, const float* __restrict__ wk,
                          const float* __restrict__ wv, const float* __restrict__ wp,
                          float* __restrict__ xr,
                          float* __restrict__ w0, float* __restrict__ w1,
                          float* __restrict__ w2, float* __restrict__ w3)
{
    const int total = NX4_ + 4 * NW4_;
    for (int i = blockIdx.x * blockDim.x + threadIdx.x; i < total;
         i += gridDim.x * blockDim.x) {
        const float4* src;
        float4* dst;
        int off;
        if (i < NX4_) { src = (const float4*)x; dst = (float4*)xr; off = i; }
        else {
            int t = i - NX4_;
            int w = t / NW4_;
            off = t - w * NW4_;
            src = (const float4*)((w == 0) ? wq : (w == 1) ? wk : (w == 2) ? wv : wp);
            dst = (float4*)((w == 0) ? w0 : (w == 1) ? w1 : (w == 2) ? w2 : w3);
        }
        float4 v = src[off];
        v.x = rtf32(v.x); v.y = rtf32(v.y); v.z = rtf32(v.z); v.w = rtf32(v.w);
        dst[off] = v;
    }
}

// ---------------- rel-position GEMM (split-K, exact fp32) ----------------
__global__ void relgemm_part(const float* __restrict__ pe, const float* __restrict__ W,
                             float* __restrict__ part)
{
    __shared__ float pes[POS_][128];
    const int tid = threadIdx.x;
    const int nb = blockIdx.x, ks = blockIdx.y;
    for (int idx = tid; idx < POS_ * 128; idx += 128) {
        int m = idx >> 7, kk = idx & 127;
        pes[m][kk] = pe[(size_t)m * HD_ + ks * 128 + kk];
    }
    __syncthreads();
    const int n = nb * 128 + tid;
    float acc[POS_];
#pragma unroll
    for (int m = 0; m < POS_; m++) acc[m] = 0.f;
    for (int kk = 0; kk < 128; kk++) {
        float w = W[(size_t)(ks * 128 + kk) * HD_ + n];
#pragma unroll
        for (int m = 0; m < POS_; m++) acc[m] = fmaf(pes[m][kk], w, acc[m]);
    }
#pragma unroll
    for (int m = 0; m < POS_; m++)
        part[((size_t)ks * POS_ + m) * HD_ + n] = acc[m];
}

__global__ void relgemm_reduce(const float* __restrict__ part, float* __restrict__ relk)
{
    int i = blockIdx.x * blockDim.x + threadIdx.x;
    if (i < POS_ * HD_) {
        float s = 0.f;
#pragma unroll
        for (int ks = 0; ks < KSPLIT_; ks++) s += part[(size_t)ks * POS_ * HD_ + i];
        relk[i] = s;
    }
}

// ---------------- chunked attention: one block per (n, h) ----------------
__global__ __launch_bounds__(128)
void attn_kernel(const float* __restrict__ q, const float* __restrict__ k,
                 const float* __restrict__ v, const float* __restrict__ relk,
                 const float* __restrict__ pds, float* __restrict__ ctx)
{
    __shared__ float qs[C_][D_ + 1];
    __shared__ float ks[CTX_][D_ + 1];
    __shared__ float vs[CTX_][D_ + 1];
    __shared__ float rks[POS_][D_ + 1];
    __shared__ float ac[C_][CTX_ + 1];
    __shared__ float bd[C_][POS_ + 1];
    __shared__ float pr[C_][CTX_ + 1];

    const int n = blockIdx.x;
    const int h = blockIdx.y;
    const int tid = threadIdx.x;   // 0..127 == d

    const float qscale = 0.08838834764831845f * 1.4426950408889634f
                       * log1pf(expf(pds[tid]));

#pragma unroll
    for (int c = 0; c < C_; c++) {
        int t = n * C_ + c;
        qs[c][tid] = (t < S_) ? q[(size_t)t * HD_ + h * D_ + tid] * qscale : 0.f;
    }
#pragma unroll
    for (int j = 0; j < CTX_; j++) {
        int p = n * C_ + j - MP_;
        bool ok = (p >= 0) && (p < S_);
        size_t off = (size_t)p * HD_ + h * D_ + tid;
        ks[j][tid] = ok ? k[off] : 0.f;
        vs[j][tid] = ok ? v[off] : 0.f;
    }
#pragma unroll
    for (int p = 0; p < POS_; p++)
        rks[p][tid] = relk[(size_t)p * HD_ + h * D_ + tid];
    __syncthreads();

    for (int slot = tid; slot < C_ * CTX_; slot += 128) {
        int c = slot / CTX_, j = slot % CTX_;
        float s = 0.f;
#pragma unroll 16
        for (int d = 0; d < D_; d++) s = fmaf(qs[c][d], ks[j][d], s);
        ac[c][j] = s;
    }
    for (int slot = tid; slot < C_ * POS_; slot += 128) {
        int c = slot / POS_, p = slot % POS_;
        float s = 0.f;
#pragma unroll 16
        for (int d = 0; d < D_; d++) s = fmaf(qs[c][d], rks[p][d], s);
        bd[c][p] = s;
    }
    __syncthreads();

    if (tid < C_) {
        const int c = tid;
        float sr[CTX_];
        float m = -1e30f;
#pragma unroll
        for (int j = 0; j < CTX_; j++) {
            int i  = c * CTX_ + j;
            int cp = i / (CTX_ + 1);
            int pp = i % (CTX_ + 1);
            float val = ac[c][j] + ((pp < POS_) ? bd[cp][pp] : 0.f);
            val = tanhf(val * 0.02f) * 50.f;
            sr[j] = val;
            m = fmaxf(m, val);
        }
        float sum = 0.f;
#pragma unroll
        for (int j = 0; j < CTX_; j++) { sr[j] = expf(sr[j] - m); sum += sr[j]; }
        float inv = 1.f / sum;
#pragma unroll
        for (int j = 0; j < CTX_; j++) pr[c][j] = sr[j] * inv;
    }
    __syncthreads();

#pragma unroll
    for (int c = 0; c < C_; c++) {
        int t = n * C_ + c;
        if (t >= S_) break;
        float o = 0.f;
#pragma unroll
        for (int j = 0; j < CTX_; j++) o = fmaf(pr[c][j], vs[j][tid], o);
        ctx[(size_t)t * HD_ + h * D_ + tid] = rtf32(o);   // pre-round for tf32 post-GEMM
    }
}

// ---------------- launch ----------------
extern "C" void kernel_launch(void* const* d_in, const int* in_sizes, int n_in,
                              void* d_out, int out_size)
{
    const float* x     = (const float*)d_in[0];
    const float* pe    = (const float*)d_in[1];
    const float* Wq    = (const float*)d_in[2];
    const float* Wk    = (const float*)d_in[3];
    const float* Wv    = (const float*)d_in[4];
    const float* Wrel  = (const float*)d_in[5];
    const float* Wpost = (const float*)d_in[6];
    const float* pds   = (const float*)d_in[7];
    float* out = (float*)d_out;

    float *pq, *pk, *pv, *pctx, *pxr, *pw0, *pw1, *pw2, *pw3, *prelk, *ppart;
    cudaGetSymbolAddress((void**)&pq,    g_q);
    cudaGetSymbolAddress((void**)&pk,    g_k);
    cudaGetSymbolAddress((void**)&pv,    g_v);
    cudaGetSymbolAddress((void**)&pctx,  g_ctx);
    cudaGetSymbolAddress((void**)&pxr,   g_xr);
    cudaGetSymbolAddress((void**)&pw0,   g_wt0);
    cudaGetSymbolAddress((void**)&pw1,   g_wt1);
    cudaGetSymbolAddress((void**)&pw2,   g_wt2);
    cudaGetSymbolAddress((void**)&pw3,   g_wt3);
    cudaGetSymbolAddress((void**)&prelk, g_relk);
    cudaGetSymbolAddress((void**)&ppart, g_relpart);

    cudaFuncSetAttribute(gemm_mma_qkv, cudaFuncAttributeMaxDynamicSharedMemorySize, GSMEM_);

    // prep: tf32-round X and weights in one launch
    round_all<<<4096, 256>>>(x, Wq, Wk, Wv, Wpost, pxr, pw0, pw1, pw2, pw3);

    // fused QKV GEMM on tensor cores (grid.z selects weight/output)
    dim3 gq(HD_ / BN_, S_ / BM_, 3);   // (16, 64, 3)
    gemm_mma_qkv<<<gq, 256, GSMEM_>>>(pxr, pw0, pw1, pw2, pq, pk, pv);

    // rel-position GEMM (tiny, split-K, exact fp32)
    relgemm_part<<<dim3(HD_ / 128, KSPLIT_), 128>>>(pe, Wrel, ppart);
    relgemm_reduce<<<(POS_ * HD_ + 255) / 256, 256>>>(ppart, prelk);

    attn_kernel<<<dim3(NBLK_, H_), 128>>>(pq, pk, pv, prelk, pds, pctx);

    // post GEMM (reuse same kernel; all three W slots point to Wpost, write out)
    dim3 gp(HD_ / BN_, S_ / BM_, 1);
    gemm_mma_qkv<<<gp, 256, GSMEM_>>>(pctx, pw3, pw3, pw3, out, out, out);
}

// round 14
// speedup vs baseline: 1.0012x; 1.0012x over previous
#include <cuda_runtime.h>
#include <math.h>
#include <stdint.h>

// ---------------- problem constants ----------------
#define S_   8192
#define H_   16
#define D_   128
#define HD_  2048
#define C_   12
#define MP_  12
#define CTX_ 24
#define POS_ 13
#define NBLK_ 683          // ceil(8192/12)
#define KSPLIT_ 16

// scratch (device globals: allocation-free rule)
__device__ float g_q[(size_t)S_ * HD_];
__device__ float g_k[(size_t)S_ * HD_];
__device__ float g_v[(size_t)S_ * HD_];
__device__ float g_ctx[(size_t)S_ * HD_];
__device__ float g_xr[(size_t)S_ * HD_];
__device__ float g_wt0[(size_t)HD_ * HD_];
__device__ float g_wt1[(size_t)HD_ * HD_];
__device__ float g_wt2[(size_t)HD_ * HD_];
__device__ float g_wt3[(size_t)HD_ * HD_];
__device__ float g_relk[(size_t)POS_ * HD_];
__device__ float g_relpart[(size_t)KSPLIT_ * POS_ * HD_];

// ---------------- small PTX helpers ----------------
__device__ __forceinline__ uint32_t smem_u32(const void* p) {
    uint32_t a;
    asm("{ .reg .u64 t; cvta.to.shared.u64 t, %1; cvt.u32.u64 %0, t; }" : "=r"(a) : "l"(p));
    return a;
}
__device__ __forceinline__ float rtf32(float x) {
    uint32_t r;
    asm("cvt.rna.tf32.f32 %0, %1;" : "=r"(r) : "f"(x));
    return __uint_as_float(r);
}
__device__ __forceinline__ void cp_async16(uint32_t dst, const void* src) {
    asm volatile("cp.async.cg.shared.global [%0], [%1], 16;" :: "r"(dst), "l"(src) : "memory");
}
__device__ __forceinline__ void cp_commit() {
    asm volatile("cp.async.commit_group;" ::: "memory");
}
__device__ __forceinline__ void mma_tf32(float* d, const uint32_t* a, const uint32_t* b) {
    asm volatile("mma.sync.aligned.m16n8k8.row.col.f32.tf32.tf32.f32 "
                 "{%0,%1,%2,%3}, {%4,%5,%6,%7}, {%8,%9}, {%0,%1,%2,%3};"
                 : "+f"(d[0]), "+f"(d[1]), "+f"(d[2]), "+f"(d[3])
                 : "r"(a[0]), "r"(a[1]), "r"(a[2]), "r"(a[3]), "r"(b[0]), "r"(b[1]));
}

// ---------------- tf32 mma.sync GEMM ----------------
// C[M,2048] = A[M,2048] @ W[2048,2048]   (W row-major [K][N])
// CTA 128x128, BK=32, 3-stage cp.async, 8 warps (4 m x 2 n), warp tile 32x64.
// One __syncthreads per 32-K iter (half of R8); refill-first; 2 CTAs/SM.
#define BM_  128
#define BN_  128
#define BK_  32
#define NST_ 3
#define ASTR_ 36            // A smem row stride (floats): (4r+c) mod 32 distinct
#define BSTR_ 136           // B smem row stride (floats), conflict-free
#define A_SZ_ (BM_ * ASTR_)             // 4608 floats
#define B_SZ_ (BK_ * BSTR_)             // 4352 floats
#define STG_SZ_ (A_SZ_ + B_SZ_)         // 8960 floats
#define GSMEM_ (NST_ * STG_SZ_ * 4)     // 107520 bytes
#define NIT_  (HD_ / BK_)               // 64

struct GemmBody {
    const float* agp;   // A global base for this thread
    const float* wgp;   // W global base for this thread
    uint32_t sb;
    int arow0, acol0, brow0, bcol0;

    __device__ __forceinline__ void stage_load(int s, int k0) const {
        uint32_t as = sb + (uint32_t)(s * STG_SZ_) * 4;
        uint32_t bs = as + A_SZ_ * 4;
        // A: 128 rows x 32 floats = 1024 16B-chunks, 4 per thread
#pragma unroll
        for (int i = 0; i < 4; i++)
            cp_async16(as + (((arow0 + i * 32) * ASTR_ + acol0) * 4),
                       agp + (size_t)(i * 32) * HD_ + k0);
        // B: 32 rows x 128 floats = 1024 16B-chunks, 4 per thread
#pragma unroll
        for (int i = 0; i < 4; i++)
            cp_async16(bs + (((brow0 + i * 8) * BSTR_ + bcol0) * 4),
                       wgp + (size_t)(k0 + i * 8) * HD_);
    }
};

__global__ void __launch_bounds__(256, 2)
gemm_mma_qkv(const float* __restrict__ A,
             const float* __restrict__ W0, const float* __restrict__ W1,
             const float* __restrict__ W2,
             float* __restrict__ C0, float* __restrict__ C1, float* __restrict__ C2)
{
    extern __shared__ float smem[];
    const int tid  = threadIdx.x;
    const int warp = tid >> 5;
    const int lane = tid & 31;
    const int wm   = warp & 3;          // m offset wm*32
    const int wn   = warp >> 2;         // n offset wn*64
    const int brow = blockIdx.y * BM_;
    const int bcol = blockIdx.x * BN_;
    const int r    = lane >> 2;         // 0..7
    const int c    = lane & 3;          // 0..3

    const float* W = (blockIdx.z == 0) ? W0 : (blockIdx.z == 1) ? W1 : W2;
    float* Cc      = (blockIdx.z == 0) ? C0 : (blockIdx.z == 1) ? C1 : C2;

    GemmBody gb;
    // A chunks: ch = tid + i*256 -> arow = ch>>3 (0..127), acol = (ch&7)*4
    gb.arow0 = tid >> 3;                // 0..31
    gb.acol0 = (tid & 7) * 4;           // 0..28
    // B chunks: ch = tid + i*256 -> brow = ch>>5 (0..31), bcol = (ch&31)*4
    gb.brow0 = tid >> 5;                // 0..7
    gb.bcol0 = (tid & 31) * 4;          // 0..124
    gb.agp = A + (size_t)(brow + gb.arow0) * HD_ + gb.acol0;
    gb.wgp = W + (size_t)gb.brow0 * HD_ + bcol + gb.bcol0;
    gb.sb  = smem_u32(smem);

    float acc[2][8][4];
#pragma unroll
    for (int i = 0; i < 2; i++)
#pragma unroll
        for (int j = 0; j < 8; j++)
#pragma unroll
            for (int e = 0; e < 4; e++) acc[i][j][e] = 0.f;

    // prologue: stages 0..NST-2
#pragma unroll
    for (int s = 0; s < NST_ - 1; s++) {
        gb.stage_load(s, s * BK_);
        cp_commit();
    }

    int sc = 0;              // stage being computed
    int sl = NST_ - 1;       // stage being loaded
    for (int it = 0; it < NIT_; it++) {
        asm volatile("cp.async.wait_group %0;" :: "n"(NST_ - 2) : "memory");
        __syncthreads();
        // barrier proves: stage sc loaded; all warps finished reading stage sl
        if (it + NST_ - 1 < NIT_)
            gb.stage_load(sl, (it + NST_ - 1) * BK_);
        cp_commit();

        const float* As = smem + sc * STG_SZ_;
        const float* Bs = As + A_SZ_;

#pragma unroll
        for (int ks = 0; ks < 4; ks++) {
            const int kc = c + ks * 8;
            uint32_t af[2][4];
#pragma unroll
            for (int i = 0; i < 2; i++) {
                const int row = wm * 32 + i * 16 + r;
                af[i][0] = __float_as_uint(As[row * ASTR_ + kc]);
                af[i][1] = __float_as_uint(As[(row + 8) * ASTR_ + kc]);
                af[i][2] = __float_as_uint(As[row * ASTR_ + kc + 4]);
                af[i][3] = __float_as_uint(As[(row + 8) * ASTR_ + kc + 4]);
            }
            uint32_t bf[8][2];
#pragma unroll
            for (int j = 0; j < 8; j++) {
                const int n = wn * 64 + j * 8 + r;
                bf[j][0] = __float_as_uint(Bs[kc * BSTR_ + n]);
                bf[j][1] = __float_as_uint(Bs[(kc + 4) * BSTR_ + n]);
            }
#pragma unroll
            for (int i = 0; i < 2; i++)
#pragma unroll
                for (int j = 0; j < 8; j++)
                    mma_tf32(acc[i][j], af[i], bf[j]);
        }
        sc = (sc == NST_ - 1) ? 0 : sc + 1;
        sl = (sl == NST_ - 1) ? 0 : sl + 1;
    }

    // epilogue: direct global stores (float2, d-fragment layout)
#pragma unroll
    for (int i = 0; i < 2; i++) {
        const int row0 = brow + wm * 32 + i * 16 + r;
#pragma unroll
        for (int j = 0; j < 8; j++) {
            const int col = bcol + wn * 64 + j * 8 + c * 2;
            *(float2*)(Cc + (size_t)row0 * HD_ + col)       = make_float2(acc[i][j][0], acc[i][j][1]);
            *(float2*)(Cc + (size_t)(row0 + 8) * HD_ + col) = make_float2(acc[i][j][2], acc[i][j][3]);
        }
    }
}

// ---------------- fused tf32 rounding (X + 4 weights in one launch) ----------------
#define NX4_ (S_ * HD_ / 4)
#define NW4_ (HD_ * HD_ / 4)
__global__ void round_all(const float* __restrict__ x,
                          const float* __restrict__ wq, const float* __restrict__ wk,
                          const float* __restrict__ wv, const float* __restrict__ wp,
                          float* __restrict__ xr,
                          float* __restrict__ w0, float* __restrict__ w1,
                          float* __restrict__ w2, float* __restrict__ w3)
{
    const int total = NX4_ + 4 * NW4_;
    for (int i = blockIdx.x * blockDim.x + threadIdx.x; i < total;
         i += gridDim.x * blockDim.x) {
        const float4* src;
        float4* dst;
        int off;
        if (i < NX4_) { src = (const float4*)x; dst = (float4*)xr; off = i; }
        else {
            int t = i - NX4_;
            int w = t / NW4_;
            off = t - w * NW4_;
            src = (const float4*)((w == 0) ? wq : (w == 1) ? wk : (w == 2) ? wv : wp);
            dst = (float4*)((w == 0) ? w0 : (w == 1) ? w1 : (w == 2) ? w2 : w3);
        }
        float4 v = src[off];
        v.x = rtf32(v.x); v.y = rtf32(v.y); v.z = rtf32(v.z); v.w = rtf32(v.w);
        dst[off] = v;
    }
}

// ---------------- rel-position GEMM (split-K, exact fp32) ----------------
__global__ void relgemm_part(const float* __restrict__ pe, const float* __restrict__ W,
                             float* __restrict__ part)
{
    __shared__ float pes[POS_][128];
    const int tid = threadIdx.x;
    const int nb = blockIdx.x, ks = blockIdx.y;
    for (int idx = tid; idx < POS_ * 128; idx += 128) {
        int m = idx >> 7, kk = idx & 127;
        pes[m][kk] = pe[(size_t)m * HD_ + ks * 128 + kk];
    }
    __syncthreads();
    const int n = nb * 128 + tid;
    float acc[POS_];
#pragma unroll
    for (int m = 0; m < POS_; m++) acc[m] = 0.f;
    for (int kk = 0; kk < 128; kk++) {
        float w = W[(size_t)(ks * 128 + kk) * HD_ + n];
#pragma unroll
        for (int m = 0; m < POS_; m++) acc[m] = fmaf(pes[m][kk], w, acc[m]);
    }
#pragma unroll
    for (int m = 0; m < POS_; m++)
        part[((size_t)ks * POS_ + m) * HD_ + n] = acc[m];
}

__global__ void relgemm_reduce(const float* __restrict__ part, float* __restrict__ relk)
{
    int i = blockIdx.x * blockDim.x + threadIdx.x;
    if (i < POS_ * HD_) {
        float s = 0.f;
#pragma unroll
        for (int ks = 0; ks < KSPLIT_; ks++) s += part[(size_t)ks * POS_ * HD_ + i];
        relk[i] = s;
    }
}

// ---------------- chunked attention: one block per (n, h) ----------------
__global__ __launch_bounds__(128)
void attn_kernel(const float* __restrict__ q, const float* __restrict__ k,
                 const float* __restrict__ v, const float* __restrict__ relk,
                 const float* __restrict__ pds, float* __restrict__ ctx)
{
    __shared__ float qs[C_][D_ + 1];
    __shared__ float ks[CTX_][D_ + 1];
    __shared__ float vs[CTX_][D_ + 1];
    __shared__ float rks[POS_][D_ + 1];
    __shared__ float ac[C_][CTX_ + 1];
    __shared__ float bd[C_][POS_ + 1];
    __shared__ float pr[C_][CTX_ + 1];

    const int n = blockIdx.x;
    const int h = blockIdx.y;
    const int tid = threadIdx.x;   // 0..127 == d

    const float qscale = 0.08838834764831845f * 1.4426950408889634f
                       * log1pf(expf(pds[tid]));

#pragma unroll
    for (int c = 0; c < C_; c++) {
        int t = n * C_ + c;
        qs[c][tid] = (t < S_) ? q[(size_t)t * HD_ + h * D_ + tid] * qscale : 0.f;
    }
#pragma unroll
    for (int j = 0; j < CTX_; j++) {
        int p = n * C_ + j - MP_;
        bool ok = (p >= 0) && (p < S_);
        size_t off = (size_t)p * HD_ + h * D_ + tid;
        ks[j][tid] = ok ? k[off] : 0.f;
        vs[j][tid] = ok ? v[off] : 0.f;
    }
#pragma unroll
    for (int p = 0; p < POS_; p++)
        rks[p][tid] = relk[(size_t)p * HD_ + h * D_ + tid];
    __syncthreads();

    for (int slot = tid; slot < C_ * CTX_; slot += 128) {
        int c = slot / CTX_, j = slot % CTX_;
        float s = 0.f;
#pragma unroll 16
        for (int d = 0; d < D_; d++) s = fmaf(qs[c][d], ks[j][d], s);
        ac[c][j] = s;
    }
    for (int slot = tid; slot < C_ * POS_; slot += 128) {
        int c = slot / POS_, p = slot % POS_;
        float s = 0.f;
#pragma unroll 16
        for (int d = 0; d < D_; d++) s = fmaf(qs[c][d], rks[p][d], s);
        bd[c][p] = s;
    }
    __syncthreads();

    if (tid < C_) {
        const int c = tid;
        float sr[CTX_];
        float m = -1e30f;
#pragma unroll
        for (int j = 0; j < CTX_; j++) {
            int i  = c * CTX_ + j;
            int cp = i / (CTX_ + 1);
            int pp = i % (CTX_ + 1);
            float val = ac[c][j] + ((pp < POS_) ? bd[cp][pp] : 0.f);
            val = tanhf(val * 0.02f) * 50.f;
            sr[j] = val;
            m = fmaxf(m, val);
        }
        float sum = 0.f;
#pragma unroll
        for (int j = 0; j < CTX_; j++) { sr[j] = expf(sr[j] - m); sum += sr[j]; }
        float inv = 1.f / sum;
#pragma unroll
        for (int j = 0; j < CTX_; j++) pr[c][j] = sr[j] * inv;
    }
    __syncthreads();

#pragma unroll
    for (int c = 0; c < C_; c++) {
        int t = n * C_ + c;
        if (t >= S_) break;
        float o = 0.f;
#pragma unroll
        for (int j = 0; j < CTX_; j++) o = fmaf(pr[c][j], vs[j][tid], o);
        ctx[(size_t)t * HD_ + h * D_ + tid] = rtf32(o);   // pre-round for tf32 post-GEMM
    }
}

// ---------------- launch ----------------
extern "C" void kernel_launch(void* const* d_in, const int* in_sizes, int n_in,
                              void* d_out, int out_size)
{
    const float* x     = (const float*)d_in[0];
    const float* pe    = (const float*)d_in[1];
    const float* Wq    = (const float*)d_in[2];
    const float* Wk    = (const float*)d_in[3];
    const float* Wv    = (const float*)d_in[4];
    const float* Wrel  = (const float*)d_in[5];
    const float* Wpost = (const float*)d_in[6];
    const float* pds   = (const float*)d_in[7];
    float* out = (float*)d_out;

    float *pq, *pk, *pv, *pctx, *pxr, *pw0, *pw1, *pw2, *pw3, *prelk, *ppart;
    cudaGetSymbolAddress((void**)&pq,    g_q);
    cudaGetSymbolAddress((void**)&pk,    g_k);
    cudaGetSymbolAddress((void**)&pv,    g_v);
    cudaGetSymbolAddress((void**)&pctx,  g_ctx);
    cudaGetSymbolAddress((void**)&pxr,   g_xr);
    cudaGetSymbolAddress((void**)&pw0,   g_wt0);
    cudaGetSymbolAddress((void**)&pw1,   g_wt1);
    cudaGetSymbolAddress((void**)&pw2,   g_wt2);
    cudaGetSymbolAddress((void**)&pw3,   g_wt3);
    cudaGetSymbolAddress((void**)&prelk, g_relk);
    cudaGetSymbolAddress((void**)&ppart, g_relpart);

    cudaFuncSetAttribute(gemm_mma_qkv, cudaFuncAttributeMaxDynamicSharedMemorySize, GSMEM_);

    // prep: tf32-round X and weights in one launch
    round_all<<<4096, 256>>>(x, Wq, Wk, Wv, Wpost, pxr, pw0, pw1, pw2, pw3);

    // fused QKV GEMM on tensor cores (grid.z selects weight/output)
    dim3 gq(HD_ / BN_, S_ / BM_, 3);   // (16, 64, 3)
    gemm_mma_qkv<<<gq, 256, GSMEM_>>>(pxr, pw0, pw1, pw2, pq, pk, pv);

    // rel-position GEMM (tiny, split-K, exact fp32)
    relgemm_part<<<dim3(HD_ / 128, KSPLIT_), 128>>>(pe, Wrel, ppart);
    relgemm_reduce<<<(POS_ * HD_ + 255) / 256, 256>>>(ppart, prelk);

    attn_kernel<<<dim3(NBLK_, H_), 128>>>(pq, pk, pv, prelk, pds, pctx);

    // post GEMM (reuse same kernel; all three W slots point to Wpost, write out)
    dim3 gp(HD_ / BN_, S_ / BM_, 1);
    gemm_mma_qkv<<<gp, 256, GSMEM_>>>(pctx, pw3, pw3, pw3, out, out, out);
}

// round 15
// speedup vs baseline: 1.0018x; 1.0006x over previous
#include <cuda_runtime.h>
#include <math.h>
#include <stdint.h>

// ---------------- problem constants ----------------
#define S_   8192
#define H_   16
#define D_   128
#define HD_  2048
#define C_   12
#define MP_  12
#define CTX_ 24
#define POS_ 13
#define NBLK_ 683          // ceil(8192/12)
#define KSPLIT_ 16

// scratch (device globals: allocation-free rule)
__device__ float g_q[(size_t)S_ * HD_];
__device__ float g_k[(size_t)S_ * HD_];
__device__ float g_v[(size_t)S_ * HD_];
__device__ float g_ctx[(size_t)S_ * HD_];
__device__ float g_xr[(size_t)S_ * HD_];
__device__ float g_wt0[(size_t)HD_ * HD_];
__device__ float g_wt1[(size_t)HD_ * HD_];
__device__ float g_wt2[(size_t)HD_ * HD_];
__device__ float g_wt3[(size_t)HD_ * HD_];
__device__ float g_relk[(size_t)POS_ * HD_];
__device__ float g_relpart[(size_t)KSPLIT_ * POS_ * HD_];

// ---------------- small PTX helpers ----------------
__device__ __forceinline__ uint32_t smem_u32(const void* p) {
    uint32_t a;
    asm("{ .reg .u64 t; cvta.to.shared.u64 t, %1; cvt.u32.u64 %0, t; }" : "=r"(a) : "l"(p));
    return a;
}
__device__ __forceinline__ float rtf32(float x) {
    uint32_t r;
    asm("cvt.rna.tf32.f32 %0, %1;" : "=r"(r) : "f"(x));
    return __uint_as_float(r);
}
__device__ __forceinline__ void cp_async16(uint32_t dst, const void* src) {
    asm volatile("cp.async.cg.shared.global [%0], [%1], 16;" :: "r"(dst), "l"(src) : "memory");
}
__device__ __forceinline__ void cp_commit() {
    asm volatile("cp.async.commit_group;" ::: "memory");
}
__device__ __forceinline__ void mma_tf32(float* d, const uint32_t* a, const uint32_t* b) {
    asm volatile("mma.sync.aligned.m16n8k8.row.col.f32.tf32.tf32.f32 "
                 "{%0,%1,%2,%3}, {%4,%5,%6,%7}, {%8,%9}, {%0,%1,%2,%3};"
                 : "+f"(d[0]), "+f"(d[1]), "+f"(d[2]), "+f"(d[3])
                 : "r"(a[0]), "r"(a[1]), "r"(a[2]), "r"(a[3]), "r"(b[0]), "r"(b[1]));
}

// ---------------- tf32 mma.sync GEMM ----------------
// C[M,2048] = A[M,2048] @ W[2048,2048]   (W row-major [K][N])
// CTA 128x128, BK=32, 3-stage cp.async, 8 warps (4 m x 2 n), warp tile 32x64.
// One __syncthreads per 32-K iter (half of R8); refill-first; 2 CTAs/SM.
#define BM_  128
#define BN_  128
#define BK_  32
#define NST_ 3
#define ASTR_ 36            // A smem row stride (floats): (4r+c) mod 32 distinct
#define BSTR_ 136           // B smem row stride (floats), conflict-free
#define A_SZ_ (BM_ * ASTR_)             // 4608 floats
#define B_SZ_ (BK_ * BSTR_)             // 4352 floats
#define STG_SZ_ (A_SZ_ + B_SZ_)         // 8960 floats
#define GSMEM_ (NST_ * STG_SZ_ * 4)     // 107520 bytes
#define NIT_  (HD_ / BK_)               // 64

struct GemmBody {
    const float* agp;   // A global base for this thread
    const float* wgp;   // W global base for this thread
    uint32_t sb;
    int arow0, acol0, brow0, bcol0;

    __device__ __forceinline__ void stage_load(int s, int k0) const {
        uint32_t as = sb + (uint32_t)(s * STG_SZ_) * 4;
        uint32_t bs = as + A_SZ_ * 4;
        // A: 128 rows x 32 floats = 1024 16B-chunks, 4 per thread
#pragma unroll
        for (int i = 0; i < 4; i++)
            cp_async16(as + (((arow0 + i * 32) * ASTR_ + acol0) * 4),
                       agp + (size_t)(i * 32) * HD_ + k0);
        // B: 32 rows x 128 floats = 1024 16B-chunks, 4 per thread
#pragma unroll
        for (int i = 0; i < 4; i++)
            cp_async16(bs + (((brow0 + i * 8) * BSTR_ + bcol0) * 4),
                       wgp + (size_t)(k0 + i * 8) * HD_);
    }
};

__global__ void __launch_bounds__(256, 2)
gemm_mma_qkv(const float* __restrict__ A,
             const float* __restrict__ W0, const float* __restrict__ W1,
             const float* __restrict__ W2,
             float* __restrict__ C0, float* __restrict__ C1, float* __restrict__ C2)
{
    extern __shared__ float smem[];
    const int tid  = threadIdx.x;
    const int warp = tid >> 5;
    const int lane = tid & 31;
    const int wm   = warp & 3;          // m offset wm*32
    const int wn   = warp >> 2;         // n offset wn*64
    const int brow = blockIdx.y * BM_;
    const int bcol = blockIdx.x * BN_;
    const int r    = lane >> 2;         // 0..7
    const int c    = lane & 3;          // 0..3

    const float* W = (blockIdx.z == 0) ? W0 : (blockIdx.z == 1) ? W1 : W2;
    float* Cc      = (blockIdx.z == 0) ? C0 : (blockIdx.z == 1) ? C1 : C2;

    GemmBody gb;
    // A chunks: ch = tid + i*256 -> arow = ch>>3 (0..127), acol = (ch&7)*4
    gb.arow0 = tid >> 3;                // 0..31
    gb.acol0 = (tid & 7) * 4;           // 0..28
    // B chunks: ch = tid + i*256 -> brow = ch>>5 (0..31), bcol = (ch&31)*4
    gb.brow0 = tid >> 5;                // 0..7
    gb.bcol0 = (tid & 31) * 4;          // 0..124
    gb.agp = A + (size_t)(brow + gb.arow0) * HD_ + gb.acol0;
    gb.wgp = W + (size_t)gb.brow0 * HD_ + bcol + gb.bcol0;
    gb.sb  = smem_u32(smem);

    float acc[2][8][4];
#pragma unroll
    for (int i = 0; i < 2; i++)
#pragma unroll
        for (int j = 0; j < 8; j++)
#pragma unroll
            for (int e = 0; e < 4; e++) acc[i][j][e] = 0.f;

    // prologue: stages 0..NST-2
#pragma unroll
    for (int s = 0; s < NST_ - 1; s++) {
        gb.stage_load(s, s * BK_);
        cp_commit();
    }

    int sc = 0;              // stage being computed
    int sl = NST_ - 1;       // stage being loaded
    for (int it = 0; it < NIT_; it++) {
        asm volatile("cp.async.wait_group %0;" :: "n"(NST_ - 2) : "memory");
        __syncthreads();
        // barrier proves: stage sc loaded; all warps finished reading stage sl
        if (it + NST_ - 1 < NIT_)
            gb.stage_load(sl, (it + NST_ - 1) * BK_);
        cp_commit();

        const float* As = smem + sc * STG_SZ_;
        const float* Bs = As + A_SZ_;

#pragma unroll
        for (int ks = 0; ks < 4; ks++) {
            const int kc = c + ks * 8;
            uint32_t af[2][4];
#pragma unroll
            for (int i = 0; i < 2; i++) {
                const int row = wm * 32 + i * 16 + r;
                af[i][0] = __float_as_uint(As[row * ASTR_ + kc]);
                af[i][1] = __float_as_uint(As[(row + 8) * ASTR_ + kc]);
                af[i][2] = __float_as_uint(As[row * ASTR_ + kc + 4]);
                af[i][3] = __float_as_uint(As[(row + 8) * ASTR_ + kc + 4]);
            }
            uint32_t bf[8][2];
#pragma unroll
            for (int j = 0; j < 8; j++) {
                const int n = wn * 64 + j * 8 + r;
                bf[j][0] = __float_as_uint(Bs[kc * BSTR_ + n]);
                bf[j][1] = __float_as_uint(Bs[(kc + 4) * BSTR_ + n]);
            }
#pragma unroll
            for (int i = 0; i < 2; i++)
#pragma unroll
                for (int j = 0; j < 8; j++)
                    mma_tf32(acc[i][j], af[i], bf[j]);
        }
        sc = (sc == NST_ - 1) ? 0 : sc + 1;
        sl = (sl == NST_ - 1) ? 0 : sl + 1;
    }

    // epilogue: direct global stores (float2, d-fragment layout)
#pragma unroll
    for (int i = 0; i < 2; i++) {
        const int row0 = brow + wm * 32 + i * 16 + r;
#pragma unroll
        for (int j = 0; j < 8; j++) {
            const int col = bcol + wn * 64 + j * 8 + c * 2;
            *(float2*)(Cc + (size_t)row0 * HD_ + col)       = make_float2(acc[i][j][0], acc[i][j][1]);
            *(float2*)(Cc + (size_t)(row0 + 8) * HD_ + col) = make_float2(acc[i][j][2], acc[i][j][3]);
        }
    }
}

// ---------------- fused tf32 rounding (X + 4 weights in one launch) ----------------
#define NX4_ (S_ * HD_ / 4)
#define NW4_ (HD_ * HD_ / 4)
__global__ void round_all(const float* __restrict__ x,
                          const float* __restrict__ wq, const float* __restrict__ wk,
                          const float* __restrict__ wv, const float* __restrict__ wp,
                          float* __restrict__ xr,
                          float* __restrict__ w0, float* __restrict__ w1,
                          float* __restrict__ w2, float* __restrict__ w3)
{
    const int total = NX4_ + 4 * NW4_;
    for (int i = blockIdx.x * blockDim.x + threadIdx.x; i < total;
         i += gridDim.x * blockDim.x) {
        const float4* src;
        float4* dst;
        int off;
        if (i < NX4_) { src = (const float4*)x; dst = (float4*)xr; off = i; }
        else {
            int t = i - NX4_;
            int w = t / NW4_;
            off = t - w * NW4_;
            src = (const float4*)((w == 0) ? wq : (w == 1) ? wk : (w == 2) ? wv : wp);
            dst = (float4*)((w == 0) ? w0 : (w == 1) ? w1 : (w == 2) ? w2 : w3);
        }
        float4 v = src[off];
        v.x = rtf32(v.x); v.y = rtf32(v.y); v.z = rtf32(v.z); v.w = rtf32(v.w);
        dst[off] = v;
    }
}

// ---------------- rel-position GEMM (split-K, exact fp32) ----------------
__global__ void relgemm_part(const float* __restrict__ pe, const float* __restrict__ W,
                             float* __restrict__ part)
{
    __shared__ float pes[POS_][128];
    const int tid = threadIdx.x;
    const int nb = blockIdx.x, ks = blockIdx.y;
    for (int idx = tid; idx < POS_ * 128; idx += 128) {
        int m = idx >> 7, kk = idx & 127;
        pes[m][kk] = pe[(size_t)m * HD_ + ks * 128 + kk];
    }
    __syncthreads();
    const int n = nb * 128 + tid;
    float acc[POS_];
#pragma unroll
    for (int m = 0; m < POS_; m++) acc[m] = 0.f;
    for (int kk = 0; kk < 128; kk++) {
        float w = W[(size_t)(ks * 128 + kk) * HD_ + n];
#pragma unroll
        for (int m = 0; m < POS_; m++) acc[m] = fmaf(pes[m][kk], w, acc[m]);
    }
#pragma unroll
    for (int m = 0; m < POS_; m++)
        part[((size_t)ks * POS_ + m) * HD_ + n] = acc[m];
}

__global__ void relgemm_reduce(const float* __restrict__ part, float* __restrict__ relk)
{
    int i = blockIdx.x * blockDim.x + threadIdx.x;
    if (i < POS_ * HD_) {
        float s = 0.f;
#pragma unroll
        for (int ks = 0; ks < KSPLIT_; ks++) s += part[(size_t)ks * POS_ * HD_ + i];
        relk[i] = s;
    }
}

// ---------------- chunked attention: one block per (n, h) ----------------
__global__ __launch_bounds__(128)
void attn_kernel(const float* __restrict__ q, const float* __restrict__ k,
                 const float* __restrict__ v, const float* __restrict__ relk,
                 const float* __restrict__ pds, float* __restrict__ ctx)
{
    __shared__ float qs[C_][D_ + 1];
    __shared__ float ks[CTX_][D_ + 1];
    __shared__ float vs[CTX_][D_ + 1];
    __shared__ float rks[POS_][D_ + 1];
    __shared__ float ac[C_][CTX_ + 1];
    __shared__ float bd[C_][POS_ + 1];
    __shared__ float pr[C_][CTX_ + 1];

    const int n = blockIdx.x;
    const int h = blockIdx.y;
    const int tid = threadIdx.x;   // 0..127 == d

    const float qscale = 0.08838834764831845f * 1.4426950408889634f
                       * log1pf(expf(pds[tid]));

#pragma unroll
    for (int c = 0; c < C_; c++) {
        int t = n * C_ + c;
        qs[c][tid] = (t < S_) ? q[(size_t)t * HD_ + h * D_ + tid] * qscale : 0.f;
    }
#pragma unroll
    for (int j = 0; j < CTX_; j++) {
        int p = n * C_ + j - MP_;
        bool ok = (p >= 0) && (p < S_);
        size_t off = (size_t)p * HD_ + h * D_ + tid;
        ks[j][tid] = ok ? k[off] : 0.f;
        vs[j][tid] = ok ? v[off] : 0.f;
    }
#pragma unroll
    for (int p = 0; p < POS_; p++)
        rks[p][tid] = relk[(size_t)p * HD_ + h * D_ + tid];
    __syncthreads();

    for (int slot = tid; slot < C_ * CTX_; slot += 128) {
        int c = slot / CTX_, j = slot % CTX_;
        float s = 0.f;
#pragma unroll 16
        for (int d = 0; d < D_; d++) s = fmaf(qs[c][d], ks[j][d], s);
        ac[c][j] = s;
    }
    for (int slot = tid; slot < C_ * POS_; slot += 128) {
        int c = slot / POS_, p = slot % POS_;
        float s = 0.f;
#pragma unroll 16
        for (int d = 0; d < D_; d++) s = fmaf(qs[c][d], rks[p][d], s);
        bd[c][p] = s;
    }
    __syncthreads();

    if (tid < C_) {
        const int c = tid;
        float sr[CTX_];
        float m = -1e30f;
#pragma unroll
        for (int j = 0; j < CTX_; j++) {
            int i  = c * CTX_ + j;
            int cp = i / (CTX_ + 1);
            int pp = i % (CTX_ + 1);
            float val = ac[c][j] + ((pp < POS_) ? bd[cp][pp] : 0.f);
            val = tanhf(val * 0.02f) * 50.f;
            sr[j] = val;
            m = fmaxf(m, val);
        }
        float sum = 0.f;
#pragma unroll
        for (int j = 0; j < CTX_; j++) { sr[j] = expf(sr[j] - m); sum += sr[j]; }
        float inv = 1.f / sum;
#pragma unroll
        for (int j = 0; j < CTX_; j++) pr[c][j] = sr[j] * inv;
    }
    __syncthreads();

#pragma unroll
    for (int c = 0; c < C_; c++) {
        int t = n * C_ + c;
        if (t >= S_) break;
        float o = 0.f;
#pragma unroll
        for (int j = 0; j < CTX_; j++) o = fmaf(pr[c][j], vs[j][tid], o);
        ctx[(size_t)t * HD_ + h * D_ + tid] = rtf32(o);   // pre-round for tf32 post-GEMM
    }
}

// ---------------- launch ----------------
extern "C" void kernel_launch(void* const* d_in, const int* in_sizes, int n_in,
                              void* d_out, int out_size)
{
    const float* x     = (const float*)d_in[0];
    const float* pe    = (const float*)d_in[1];
    const float* Wq    = (const float*)d_in[2];
    const float* Wk    = (const float*)d_in[3];
    const float* Wv    = (const float*)d_in[4];
    const float* Wrel  = (const float*)d_in[5];
    const float* Wpost = (const float*)d_in[6];
    const float* pds   = (const float*)d_in[7];
    float* out = (float*)d_out;

    float *pq, *pk, *pv, *pctx, *pxr, *pw0, *pw1, *pw2, *pw3, *prelk, *ppart;
    cudaGetSymbolAddress((void**)&pq,    g_q);
    cudaGetSymbolAddress((void**)&pk,    g_k);
    cudaGetSymbolAddress((void**)&pv,    g_v);
    cudaGetSymbolAddress((void**)&pctx,  g_ctx);
    cudaGetSymbolAddress((void**)&pxr,   g_xr);
    cudaGetSymbolAddress((void**)&pw0,   g_wt0);
    cudaGetSymbolAddress((void**)&pw1,   g_wt1);
    cudaGetSymbolAddress((void**)&pw2,   g_wt2);
    cudaGetSymbolAddress((void**)&pw3,   g_wt3);
    cudaGetSymbolAddress((void**)&prelk, g_relk);
    cudaGetSymbolAddress((void**)&ppart, g_relpart);

    cudaFuncSetAttribute(gemm_mma_qkv, cudaFuncAttributeMaxDynamicSharedMemorySize, GSMEM_);

    // prep: tf32-round X and weights in one launch
    round_all<<<4096, 256>>>(x, Wq, Wk, Wv, Wpost, pxr, pw0, pw1, pw2, pw3);

    // fused QKV GEMM on tensor cores (grid.z selects weight/output)
    dim3 gq(HD_ / BN_, S_ / BM_, 3);   // (16, 64, 3)
    gemm_mma_qkv<<<gq, 256, GSMEM_>>>(pxr, pw0, pw1, pw2, pq, pk, pv);

    // rel-position GEMM (tiny, split-K, exact fp32)
    relgemm_part<<<dim3(HD_ / 128, KSPLIT_), 128>>>(pe, Wrel, ppart);
    relgemm_reduce<<<(POS_ * HD_ + 255) / 256, 256>>>(ppart, prelk);

    attn_kernel<<<dim3(NBLK_, H_), 128>>>(pq, pk, pv, prelk, pds, pctx);

    // post GEMM (reuse same kernel; all three W slots point to Wpost, write out)
    dim3 gp(HD_ / BN_, S_ / BM_, 1);
    gemm_mma_qkv<<<gp, 256, GSMEM_>>>(pctx, pw3, pw3, pw3, out, out, out);
}